// round 1
// baseline (speedup 1.0000x reference)
#include <cuda_runtime.h>
#include <math.h>

#define NB 16
#define NS 2048
#define ND 1024
#define NH 128

// Scratch for Q/K/V projections: 3 x 16MB
__device__ float g_q[(size_t)NB * NS * NH];
__device__ float g_k[(size_t)NB * NS * NH];
__device__ float g_v[(size_t)NB * NS * NH];

// ---------------------------------------------------------------------------
// Projection GEMM: [M=B*S, D] x [D, H] -> [M, H], for Wq/Wk/Wv (blockIdx.y)
// BM=128, BN=128(=H), BK=8, 256 threads, 8x8 per thread (split 4+4 mapping)
// ---------------------------------------------------------------------------
__global__ __launch_bounds__(256, 2)
void proj_kernel(const float* __restrict__ X,
                 const float* __restrict__ Wq,
                 const float* __restrict__ Wk,
                 const float* __restrict__ Wv)
{
    __shared__ float Ast[8][128];   // [k][row]
    __shared__ float Ws[8][128];    // [k][col]

    const float* W;
    float* O;
    if (blockIdx.y == 0)      { W = Wq; O = g_q; }
    else if (blockIdx.y == 1) { W = Wk; O = g_k; }
    else                      { W = Wv; O = g_v; }

    const int tid = threadIdx.x;
    const int tx = tid & 15;        // col group
    const int ty = tid >> 4;        // row group
    const size_t m0 = (size_t)blockIdx.x * 128;

    const int arow = tid >> 1;          // 0..127
    const int acol = (tid & 1) * 4;     // 0 or 4
    const int wrow = tid >> 5;          // 0..7
    const int wcol = (tid & 31) * 4;    // 0..124

    float acc[8][8];
#pragma unroll
    for (int i = 0; i < 8; i++)
#pragma unroll
        for (int j = 0; j < 8; j++) acc[i][j] = 0.f;

    for (int k0 = 0; k0 < ND; k0 += 8) {
        float4 a = *(const float4*)&X[(m0 + arow) * ND + k0 + acol];
        float4 w = *(const float4*)&W[(size_t)(k0 + wrow) * NH + wcol];
        __syncthreads();
        Ast[acol + 0][arow] = a.x;
        Ast[acol + 1][arow] = a.y;
        Ast[acol + 2][arow] = a.z;
        Ast[acol + 3][arow] = a.w;
        *(float4*)&Ws[wrow][wcol] = w;
        __syncthreads();
#pragma unroll
        for (int k = 0; k < 8; k++) {
            float av[8], bv[8];
            *(float4*)&av[0] = *(const float4*)&Ast[k][ty * 4];
            *(float4*)&av[4] = *(const float4*)&Ast[k][64 + ty * 4];
            *(float4*)&bv[0] = *(const float4*)&Ws[k][tx * 4];
            *(float4*)&bv[4] = *(const float4*)&Ws[k][64 + tx * 4];
#pragma unroll
            for (int i = 0; i < 8; i++)
#pragma unroll
                for (int j = 0; j < 8; j++)
                    acc[i][j] += av[i] * bv[j];
        }
    }

#pragma unroll
    for (int i = 0; i < 8; i++) {
        int rloc = (i < 4) ? (ty * 4 + i) : (64 + ty * 4 + (i - 4));
        size_t r = m0 + rloc;
        float4 o0 = make_float4(acc[i][0], acc[i][1], acc[i][2], acc[i][3]);
        float4 o1 = make_float4(acc[i][4], acc[i][5], acc[i][6], acc[i][7]);
        *(float4*)&O[r * NH + tx * 4] = o0;
        *(float4*)&O[r * NH + 64 + tx * 4] = o1;
    }
}

// ---------------------------------------------------------------------------
// Causal flash attention: BQ=64 query rows x BK=64 key cols per tile, H=128.
// smem: Qs 64x128 | Kts 128x64 (xor-swizzled 16B chunks) | Vs 64x128 | Ps 64x64
// Thread map: 256 thr; rx=tid&15, ry=tid>>4.
//   S tile:  rows ry*4..+3, cols rx*4..+3  (4x4 per thread)
//   O tile:  rows ry*4..+3, cols rx*8..+7  (4x8 per thread)
// Row groups identical -> softmax stats live in registers, half-warp shuffles.
// ---------------------------------------------------------------------------
#define ATTN_SMEM_FLOATS (8192 + 8192 + 8192 + 4096)

#define PVSTEP(pc, va, vb) \
    o[0] += (pc) * (va).x; o[1] += (pc) * (va).y; \
    o[2] += (pc) * (va).z; o[3] += (pc) * (va).w; \
    o[4] += (pc) * (vb).x; o[5] += (pc) * (vb).y; \
    o[6] += (pc) * (vb).z; o[7] += (pc) * (vb).w;

#define SSTEP(qc, kt) \
    s[0] += (qc) * (kt).x; s[1] += (qc) * (kt).y; \
    s[2] += (qc) * (kt).z; s[3] += (qc) * (kt).w;

__global__ __launch_bounds__(256, 2)
void attn_kernel(float* __restrict__ out)
{
    extern __shared__ float sm[];
    float* Qs  = sm;             // [64][128]
    float* Kts = sm + 8192;      // [128][64] swizzled
    float* Vs  = sm + 16384;     // [64][128]
    float* Ps  = sm + 24576;     // [64][64]

    const int b  = blockIdx.y;
    const int qt = (int)(gridDim.x - 1) - (int)blockIdx.x;  // heavy tiles first
    const int q0 = qt * 64;
    const int tid = threadIdx.x;
    const int rx = tid & 15;
    const int ry = tid >> 4;

    const float* Qg = g_q + ((size_t)b * NS + q0) * NH;
    const float* Kg = g_k + (size_t)b * NS * NH;
    const float* Vg = g_v + (size_t)b * NS * NH;

    // Load Q tile (contiguous 64x128), pre-scaled by 1/sqrt(H)
    const float qscale = 0.08838834764831845f;  // 128^-0.5
    for (int f = tid; f < 2048; f += 256) {
        float4 v = *(const float4*)&Qg[f * 4];
        v.x *= qscale; v.y *= qscale; v.z *= qscale; v.w *= qscale;
        *(float4*)&Qs[f * 4] = v;
    }

    float oacc[4][8];
#pragma unroll
    for (int i = 0; i < 4; i++)
#pragma unroll
        for (int c = 0; c < 8; c++) oacc[i][c] = 0.f;
    float m_i[4] = {-INFINITY, -INFINITY, -INFINITY, -INFINITY};
    float l_i[4] = {0.f, 0.f, 0.f, 0.f};

    for (int jt = 0; jt <= qt; jt++) {
        const float* Kgj = Kg + (size_t)(jt * 64) * NH;
        const float* Vgj = Vg + (size_t)(jt * 64) * NH;

        __syncthreads();  // prior tile's P/V/K reads complete

        // V tile: contiguous copy
        for (int f = tid; f < 2048; f += 256)
            *(float4*)&Vs[f * 4] = *(const float4*)&Vgj[f * 4];

        // K tile: transpose into Kts[k][col], xor-swizzle 16B chunks:
        // physical chunk p = (col>>2) ^ (k & 15)
#pragma unroll
        for (int it = 0; it < 8; it++) {
            int f = tid * 8 + it;
            int col = f >> 5;            // key row 0..63
            int k = (f & 31) * 4;        // head dim 0..124
            float4 v = *(const float4*)&Kgj[col * NH + k];
            float vv[4] = {v.x, v.y, v.z, v.w};
#pragma unroll
            for (int t = 0; t < 4; t++) {
                int kk = k + t;
                int p = (col >> 2) ^ (kk & 15);
                Kts[kk * 64 + p * 4 + (col & 3)] = vv[t];
            }
        }
        __syncthreads();  // tiles (and Qs on first iter) visible

        // ---- S = Q K^T (4x4 per thread) ----
        float sacc[4][4];
#pragma unroll
        for (int i = 0; i < 4; i++)
#pragma unroll
            for (int j = 0; j < 4; j++) sacc[i][j] = 0.f;

#pragma unroll 4
        for (int k = 0; k < NH; k += 4) {
            float4 kt0, kt1, kt2, kt3;
            {
                int p0 = rx ^ ((k + 0) & 15);
                int p1 = rx ^ ((k + 1) & 15);
                int p2 = rx ^ ((k + 2) & 15);
                int p3 = rx ^ ((k + 3) & 15);
                kt0 = *(const float4*)&Kts[(k + 0) * 64 + p0 * 4];
                kt1 = *(const float4*)&Kts[(k + 1) * 64 + p1 * 4];
                kt2 = *(const float4*)&Kts[(k + 2) * 64 + p2 * 4];
                kt3 = *(const float4*)&Kts[(k + 3) * 64 + p3 * 4];
            }
#pragma unroll
            for (int i = 0; i < 4; i++) {
                float4 q = *(const float4*)&Qs[(ry * 4 + i) * NH + k];
                float* s = sacc[i];
                SSTEP(q.x, kt0);
                SSTEP(q.y, kt1);
                SSTEP(q.z, kt2);
                SSTEP(q.w, kt3);
            }
        }

        // ---- causal mask on diagonal tile ----
        if (jt == qt) {
#pragma unroll
            for (int i = 0; i < 4; i++)
#pragma unroll
                for (int j = 0; j < 4; j++)
                    if (rx * 4 + j > ry * 4 + i) sacc[i][j] = -INFINITY;
        }

        // ---- online softmax (per-row, redundantly in each half-warp) ----
#pragma unroll
        for (int i = 0; i < 4; i++) {
            float mx = fmaxf(fmaxf(sacc[i][0], sacc[i][1]),
                             fmaxf(sacc[i][2], sacc[i][3]));
            mx = fmaxf(mx, __shfl_xor_sync(0xffffffffu, mx, 8));
            mx = fmaxf(mx, __shfl_xor_sync(0xffffffffu, mx, 4));
            mx = fmaxf(mx, __shfl_xor_sync(0xffffffffu, mx, 2));
            mx = fmaxf(mx, __shfl_xor_sync(0xffffffffu, mx, 1));
            float m_new = fmaxf(m_i[i], mx);
            float scale = __expf(m_i[i] - m_new);
            float rs = 0.f;
#pragma unroll
            for (int j = 0; j < 4; j++) {
                float p = __expf(sacc[i][j] - m_new);
                sacc[i][j] = p;
                rs += p;
            }
            rs += __shfl_xor_sync(0xffffffffu, rs, 8);
            rs += __shfl_xor_sync(0xffffffffu, rs, 4);
            rs += __shfl_xor_sync(0xffffffffu, rs, 2);
            rs += __shfl_xor_sync(0xffffffffu, rs, 1);
            l_i[i] = l_i[i] * scale + rs;
            m_i[i] = m_new;
#pragma unroll
            for (int c = 0; c < 8; c++) oacc[i][c] *= scale;
        }

        // ---- write P to smem ----
#pragma unroll
        for (int i = 0; i < 4; i++) {
            float4 p4 = make_float4(sacc[i][0], sacc[i][1], sacc[i][2], sacc[i][3]);
            *(float4*)&Ps[(ry * 4 + i) * 64 + rx * 4] = p4;
        }
        __syncthreads();  // P visible

        // ---- O += P V (4 rows x 8 cols per thread) ----
#pragma unroll 2
        for (int j = 0; j < 64; j += 4) {
            float4 v0a = *(const float4*)&Vs[(j + 0) * NH + rx * 8];
            float4 v0b = *(const float4*)&Vs[(j + 0) * NH + rx * 8 + 4];
            float4 v1a = *(const float4*)&Vs[(j + 1) * NH + rx * 8];
            float4 v1b = *(const float4*)&Vs[(j + 1) * NH + rx * 8 + 4];
            float4 v2a = *(const float4*)&Vs[(j + 2) * NH + rx * 8];
            float4 v2b = *(const float4*)&Vs[(j + 2) * NH + rx * 8 + 4];
            float4 v3a = *(const float4*)&Vs[(j + 3) * NH + rx * 8];
            float4 v3b = *(const float4*)&Vs[(j + 3) * NH + rx * 8 + 4];
#pragma unroll
            for (int i = 0; i < 4; i++) {
                float4 p = *(const float4*)&Ps[(ry * 4 + i) * 64 + j];
                float* o = oacc[i];
                PVSTEP(p.x, v0a, v0b);
                PVSTEP(p.y, v1a, v1b);
                PVSTEP(p.z, v2a, v2b);
                PVSTEP(p.w, v3a, v3b);
            }
        }
    }

    // ---- normalize and write out ----
    float* Og = out + ((size_t)b * NS + q0) * NH;
#pragma unroll
    for (int i = 0; i < 4; i++) {
        float inv = 1.0f / l_i[i];
        int row = ry * 4 + i;
        float4 r0 = make_float4(oacc[i][0] * inv, oacc[i][1] * inv,
                                oacc[i][2] * inv, oacc[i][3] * inv);
        float4 r1 = make_float4(oacc[i][4] * inv, oacc[i][5] * inv,
                                oacc[i][6] * inv, oacc[i][7] * inv);
        *(float4*)&Og[row * NH + rx * 8] = r0;
        *(float4*)&Og[row * NH + rx * 8 + 4] = r1;
    }
}

extern "C" void kernel_launch(void* const* d_in, const int* in_sizes, int n_in,
                              void* d_out, int out_size)
{
    const float* X  = (const float*)d_in[0];
    const float* Wq = (const float*)d_in[1];
    const float* Wk = (const float*)d_in[2];
    const float* Wv = (const float*)d_in[3];
    float* out = (float*)d_out;

    // Projections: grid (M/128, 3)
    dim3 pgrid((NB * NS) / 128, 3);
    proj_kernel<<<pgrid, 256>>>(X, Wq, Wk, Wv);

    // Attention: grid (S/64 query tiles, B batches)
    int smem_bytes = ATTN_SMEM_FLOATS * (int)sizeof(float);  // 114688
    cudaFuncSetAttribute(attn_kernel,
                         cudaFuncAttributeMaxDynamicSharedMemorySize, smem_bytes);
    dim3 agrid(NS / 64, NB);
    attn_kernel<<<agrid, 256, smem_bytes>>>(out);
}

// round 4
// speedup vs baseline: 1.7984x; 1.7984x over previous
#include <cuda_runtime.h>
#include <math.h>
#include <stdint.h>

#define NB 16
#define NS 2048
#define ND 1024
#define NH 128

// Scratch for Q/K/V projections
__device__ float g_q[(size_t)NB * NS * NH];
__device__ float g_k[(size_t)NB * NS * NH];
__device__ float g_v[(size_t)NB * NS * NH];

// ---------------------------------------------------------------------------
// Helpers
// ---------------------------------------------------------------------------
__device__ __forceinline__ uint32_t smem_u32(const void* p) {
    uint32_t a;
    asm("{ .reg .u64 t; cvta.to.shared.u64 t, %1; cvt.u32.u64 %0, t; }"
        : "=r"(a) : "l"(p));
    return a;
}

__device__ __forceinline__ void cp16(uint32_t dst, const float* src) {
    uint64_t g;
    asm("cvta.to.global.u64 %0, %1;" : "=l"(g) : "l"(src));
    asm volatile("cp.async.ca.shared.global [%0], [%1], 16;"
                 :: "r"(dst), "l"(g) : "memory");
}

#define CP_COMMIT() asm volatile("cp.async.commit_group;" ::: "memory")
#define CP_WAIT0()  asm volatile("cp.async.wait_group 0;" ::: "memory")

// D += A(16x8) * B(8x8), tf32
__device__ __forceinline__ void mma_tf32(float* c,
    uint32_t a0, uint32_t a1, uint32_t a2, uint32_t a3,
    uint32_t b0, uint32_t b1)
{
    asm volatile(
        "mma.sync.aligned.m16n8k8.row.col.f32.tf32.tf32.f32 "
        "{%0,%1,%2,%3}, {%4,%5,%6,%7}, {%8,%9}, {%0,%1,%2,%3};"
        : "+f"(c[0]), "+f"(c[1]), "+f"(c[2]), "+f"(c[3])
        : "r"(a0), "r"(a1), "r"(a2), "r"(a3), "r"(b0), "r"(b1));
}

// 3xTF32 split: hi = exact-tf32 head (mask), lo = exact fp32 residual
__device__ __forceinline__ void split2(uint32_t w, uint32_t& hi, uint32_t& lo) {
    hi = w & 0xffffe000u;
    lo = __float_as_uint(__uint_as_float(w) - __uint_as_float(hi));
}

// C += A*B at near-fp32 precision: Ah*Bh + Ah*Bl + Al*Bh
__device__ __forceinline__ void mma3(float* c,
    const uint32_t* ah, const uint32_t* al,
    uint32_t bh0, uint32_t bh1, uint32_t bl0, uint32_t bl1)
{
    mma_tf32(c, ah[0], ah[1], ah[2], ah[3], bh0, bh1);
    mma_tf32(c, ah[0], ah[1], ah[2], ah[3], bl0, bl1);
    mma_tf32(c, al[0], al[1], al[2], al[3], bh0, bh1);
}

// ---------------------------------------------------------------------------
// QKV projection GEMM on tensor cores (3xTF32).
// grid (3, 256): blockIdx.x = matrix, blockIdx.y = 128-row m-tile.
// CTA 128x128, BK=32, double-buffered cp.async.
// 8 warps: wm = wid>>1 (4), wn = wid&1 (2); warp tile 32(M) x 64(N).
// ---------------------------------------------------------------------------
#define PJ_A_STRIDE 36
#define PJ_B_STRIDE 136
#define PJ_A_BYTES (128 * PJ_A_STRIDE * 4)      // 18432
#define PJ_B_BYTES (32 * PJ_B_STRIDE * 4)       // 17408
#define PJ_SMEM (2 * PJ_A_BYTES + 2 * PJ_B_BYTES)  // 71680

__global__ __launch_bounds__(256, 2)
void proj_mma(const float* __restrict__ X,
              const float* __restrict__ Wq,
              const float* __restrict__ Wk,
              const float* __restrict__ Wv)
{
    extern __shared__ float sm[];
    const uint32_t sbase = smem_u32(sm);
    const int tid = threadIdx.x;
    const int wid = tid >> 5;
    const int lane = tid & 31;
    const int u = lane >> 2;        // 0..7
    const int v = lane & 3;         // 0..3
    const int wm = wid >> 1;        // 0..3
    const int wn = wid & 1;         // 0..1

    const int mat = blockIdx.x;
    const size_t m0 = (size_t)blockIdx.y * 128;
    const float* W = (mat == 0) ? Wq : (mat == 1) ? Wk : Wv;
    float* O = (mat == 0) ? g_q : (mat == 1) ? g_k : g_v;

    auto copy_tile = [&](int kt, int buf) {
        const int k0 = kt * 32;
        uint32_t abase = sbase + buf * PJ_A_BYTES;
        uint32_t bbase = sbase + 2 * PJ_A_BYTES + buf * PJ_B_BYTES;
#pragma unroll
        for (int i = 0; i < 4; i++) {
            int e = i * 256 + tid;
            int row = e >> 3, c = e & 7;
            cp16(abase + (row * PJ_A_STRIDE + c * 4) * 4,
                 X + (m0 + row) * ND + k0 + c * 4);
        }
#pragma unroll
        for (int i = 0; i < 4; i++) {
            int e = i * 256 + tid;
            int row = e >> 5, c = e & 31;
            cp16(bbase + (row * PJ_B_STRIDE + c * 4) * 4,
                 W + (size_t)(k0 + row) * NH + c * 4);
        }
    };

    float acc[2][8][4];
#pragma unroll
    for (int mt = 0; mt < 2; mt++)
#pragma unroll
        for (int nt = 0; nt < 8; nt++)
#pragma unroll
            for (int j = 0; j < 4; j++) acc[mt][nt][j] = 0.f;

    copy_tile(0, 0);
    CP_COMMIT();

    for (int it = 0; it < 32; it++) {
        const int buf = it & 1;
        CP_WAIT0();
        __syncthreads();
        if (it < 31) {
            copy_tile(it + 1, buf ^ 1);
            CP_COMMIT();
        }

        const uint32_t* As = (const uint32_t*)sm + buf * (PJ_A_BYTES / 4);
        const uint32_t* Bs = (const uint32_t*)sm + 2 * (PJ_A_BYTES / 4)
                                                + buf * (PJ_B_BYTES / 4);
#pragma unroll
        for (int ks = 0; ks < 4; ks++) {
            uint32_t ah[2][4], al[2][4];
#pragma unroll
            for (int mt = 0; mt < 2; mt++) {
                int r = wm * 32 + mt * 16 + u;
                int wq = r * PJ_A_STRIDE + ks * 8 + v;
                split2(As[wq],                      ah[mt][0], al[mt][0]);
                split2(As[wq + 8 * PJ_A_STRIDE],    ah[mt][1], al[mt][1]);
                split2(As[wq + 4],                  ah[mt][2], al[mt][2]);
                split2(As[wq + 8 * PJ_A_STRIDE + 4],ah[mt][3], al[mt][3]);
            }
#pragma unroll
            for (int nt = 0; nt < 8; nt++) {
                int w0 = (ks * 8 + v) * PJ_B_STRIDE + wn * 64 + nt * 8 + u;
                uint32_t bh0, bl0, bh1, bl1;
                split2(Bs[w0],                  bh0, bl0);
                split2(Bs[w0 + 4 * PJ_B_STRIDE],bh1, bl1);
#pragma unroll
                for (int mt = 0; mt < 2; mt++)
                    mma3(acc[mt][nt], ah[mt], al[mt], bh0, bh1, bl0, bl1);
            }
        }
    }

#pragma unroll
    for (int mt = 0; mt < 2; mt++) {
#pragma unroll
        for (int nt = 0; nt < 8; nt++) {
            size_t r = m0 + wm * 32 + mt * 16 + u;
            int c = wn * 64 + nt * 8 + v * 2;
            *(float2*)&O[r * NH + c] =
                make_float2(acc[mt][nt][0], acc[mt][nt][1]);
            *(float2*)&O[(r + 8) * NH + c] =
                make_float2(acc[mt][nt][2], acc[mt][nt][3]);
        }
    }
}

// ---------------------------------------------------------------------------
// Causal flash attention on tensor cores (3xTF32).
// grid (16, 16): qt = 15 - blockIdx.x (heavy first), b = blockIdx.y.
// CTA: 256 thr, BQ=128 (warp owns 16 q-rows), BKV=64, H=128.
// ---------------------------------------------------------------------------
#define AT_Q_STRIDE 132
#define AT_K_STRIDE 132
#define AT_V_STRIDE 136
#define AT_P_STRIDE 68
#define AT_Q_WORDS (128 * AT_Q_STRIDE)
#define AT_K_WORDS (64 * AT_K_STRIDE)
#define AT_V_WORDS (64 * AT_V_STRIDE)
#define AT_P_WORDS (128 * AT_P_STRIDE)
#define AT_K_OFF  AT_Q_WORDS
#define AT_V_OFF  (AT_K_OFF + AT_K_WORDS)
#define AT_P_OFF  (AT_V_OFF + AT_V_WORDS)
#define AT_SMEM_BYTES ((AT_P_OFF + AT_P_WORDS) * 4)   // 171008

__global__ __launch_bounds__(256, 1)
void attn_mma(float* __restrict__ out)
{
    extern __shared__ float sm[];
    const uint32_t sbase = smem_u32(sm);
    const int tid = threadIdx.x;
    const int wid = tid >> 5;
    const int lane = tid & 31;
    const int u = lane >> 2;
    const int v = lane & 3;

    const int b  = blockIdx.y;
    const int qt = (int)(gridDim.x - 1) - (int)blockIdx.x;
    const int q0 = qt * 128;

    const float* Qg = g_q + ((size_t)b * NS + q0) * NH;
    const float* Kg = g_k + (size_t)b * NS * NH;
    const float* Vg = g_v + (size_t)b * NS * NH;

#pragma unroll
    for (int i = 0; i < 16; i++) {
        int row = i * 8 + wid;
        cp16(sbase + (row * AT_Q_STRIDE + lane * 4) * 4,
             Qg + row * NH + lane * 4);
    }
    CP_COMMIT();

    float oacc[16][4];
#pragma unroll
    for (int nt = 0; nt < 16; nt++)
#pragma unroll
        for (int j = 0; j < 4; j++) oacc[nt][j] = 0.f;
    float m_lo = -INFINITY, m_hi = -INFINITY;
    float l_lo = 0.f, l_hi = 0.f;

    const float qscale = 0.08838834764831845f;   // 128^-0.5
    const int njt = 2 * qt + 2;

    for (int jt = 0; jt < njt; jt++) {
        __syncthreads();
        const float* Kt = Kg + (size_t)(jt * 64) * NH;
        const float* Vt = Vg + (size_t)(jt * 64) * NH;
#pragma unroll
        for (int i = 0; i < 8; i++) {
            int row = i * 8 + wid;
            cp16(sbase + (AT_K_OFF + row * AT_K_STRIDE + lane * 4) * 4,
                 Kt + row * NH + lane * 4);
            cp16(sbase + (AT_V_OFF + row * AT_V_STRIDE + lane * 4) * 4,
                 Vt + row * NH + lane * 4);
        }
        CP_COMMIT();
        CP_WAIT0();
        __syncthreads();

        const uint32_t* Qs = (const uint32_t*)sm;
        const uint32_t* Ks = (const uint32_t*)sm + AT_K_OFF;
        const uint32_t* Vs = (const uint32_t*)sm + AT_V_OFF;

        // ---- S = Q K^T ----
        float sacc[8][4];
#pragma unroll
        for (int nt = 0; nt < 8; nt++)
#pragma unroll
            for (int j = 0; j < 4; j++) sacc[nt][j] = 0.f;

#pragma unroll
        for (int ks = 0; ks < 16; ks++) {
            int r = wid * 16 + u;
            int wq = r * AT_Q_STRIDE + ks * 8 + v;
            uint32_t ah[4], al[4];
            split2(Qs[wq],                      ah[0], al[0]);
            split2(Qs[wq + 8 * AT_Q_STRIDE],    ah[1], al[1]);
            split2(Qs[wq + 4],                  ah[2], al[2]);
            split2(Qs[wq + 8 * AT_Q_STRIDE + 4],ah[3], al[3]);
#pragma unroll
            for (int nt = 0; nt < 8; nt++) {
                int wk = (nt * 8 + u) * AT_K_STRIDE + ks * 8 + v;
                uint32_t bh0, bl0, bh1, bl1;
                split2(Ks[wk],     bh0, bl0);
                split2(Ks[wk + 4], bh1, bl1);
                mma3(sacc[nt], ah, al, bh0, bh1, bl0, bl1);
            }
        }

        // scale + causal mask
        const int row_lo = q0 + wid * 16 + u;
        const int row_hi = row_lo + 8;
        if (jt >= 2 * qt) {
#pragma unroll
            for (int nt = 0; nt < 8; nt++) {
#pragma unroll
                for (int j = 0; j < 4; j++) {
                    int col = jt * 64 + nt * 8 + v * 2 + (j & 1);
                    int row = (j < 2) ? row_lo : row_hi;
                    sacc[nt][j] = (col > row) ? -INFINITY
                                              : sacc[nt][j] * qscale;
                }
            }
        } else {
#pragma unroll
            for (int nt = 0; nt < 8; nt++)
#pragma unroll
                for (int j = 0; j < 4; j++) sacc[nt][j] *= qscale;
        }

        // ---- online softmax ----
        float mx_lo = -INFINITY, mx_hi = -INFINITY;
#pragma unroll
        for (int nt = 0; nt < 8; nt++) {
            mx_lo = fmaxf(mx_lo, fmaxf(sacc[nt][0], sacc[nt][1]));
            mx_hi = fmaxf(mx_hi, fmaxf(sacc[nt][2], sacc[nt][3]));
        }
        mx_lo = fmaxf(mx_lo, __shfl_xor_sync(0xffffffffu, mx_lo, 1));
        mx_lo = fmaxf(mx_lo, __shfl_xor_sync(0xffffffffu, mx_lo, 2));
        mx_hi = fmaxf(mx_hi, __shfl_xor_sync(0xffffffffu, mx_hi, 1));
        mx_hi = fmaxf(mx_hi, __shfl_xor_sync(0xffffffffu, mx_hi, 2));

        float mn_lo = fmaxf(m_lo, mx_lo);
        float mn_hi = fmaxf(m_hi, mx_hi);
        float sc_lo = __expf(m_lo - mn_lo);
        float sc_hi = __expf(m_hi - mn_hi);
        m_lo = mn_lo; m_hi = mn_hi;

        float rs_lo = 0.f, rs_hi = 0.f;
#pragma unroll
        for (int nt = 0; nt < 8; nt++) {
            sacc[nt][0] = __expf(sacc[nt][0] - mn_lo);
            sacc[nt][1] = __expf(sacc[nt][1] - mn_lo);
            sacc[nt][2] = __expf(sacc[nt][2] - mn_hi);
            sacc[nt][3] = __expf(sacc[nt][3] - mn_hi);
            rs_lo += sacc[nt][0] + sacc[nt][1];
            rs_hi += sacc[nt][2] + sacc[nt][3];
        }
        rs_lo += __shfl_xor_sync(0xffffffffu, rs_lo, 1);
        rs_lo += __shfl_xor_sync(0xffffffffu, rs_lo, 2);
        rs_hi += __shfl_xor_sync(0xffffffffu, rs_hi, 1);
        rs_hi += __shfl_xor_sync(0xffffffffu, rs_hi, 2);
        l_lo = l_lo * sc_lo + rs_lo;
        l_hi = l_hi * sc_hi + rs_hi;

#pragma unroll
        for (int nt = 0; nt < 16; nt++) {
            oacc[nt][0] *= sc_lo; oacc[nt][1] *= sc_lo;
            oacc[nt][2] *= sc_hi; oacc[nt][3] *= sc_hi;
        }
        float* Ps = sm + AT_P_OFF;
        {
            int r = wid * 16 + u;
#pragma unroll
            for (int nt = 0; nt < 8; nt++) {
                int c = nt * 8 + v * 2;
                *(float2*)&Ps[r * AT_P_STRIDE + c] =
                    make_float2(sacc[nt][0], sacc[nt][1]);
                *(float2*)&Ps[(r + 8) * AT_P_STRIDE + c] =
                    make_float2(sacc[nt][2], sacc[nt][3]);
            }
        }
        __syncwarp();

        // ---- O += P V ----
        const uint32_t* Psu = (const uint32_t*)sm + AT_P_OFF;
#pragma unroll
        for (int kk = 0; kk < 8; kk++) {
            int r = wid * 16 + u;
            int wp = r * AT_P_STRIDE + kk * 8 + v;
            uint32_t ah[4], al[4];
            split2(Psu[wp],                      ah[0], al[0]);
            split2(Psu[wp + 8 * AT_P_STRIDE],    ah[1], al[1]);
            split2(Psu[wp + 4],                  ah[2], al[2]);
            split2(Psu[wp + 8 * AT_P_STRIDE + 4],ah[3], al[3]);
#pragma unroll
            for (int nt = 0; nt < 16; nt++) {
                int wv = (kk * 8 + v) * AT_V_STRIDE + nt * 8 + u;
                uint32_t bh0, bl0, bh1, bl1;
                split2(Vs[wv],                    bh0, bl0);
                split2(Vs[wv + 4 * AT_V_STRIDE],  bh1, bl1);
                mma3(oacc[nt], ah, al, bh0, bh1, bl0, bl1);
            }
        }
    }

    // ---- normalize + write ----
    float inv_lo = 1.0f / l_lo;
    float inv_hi = 1.0f / l_hi;
    float* Og = out + ((size_t)b * NS + q0) * NH;
    int r = wid * 16 + u;
#pragma unroll
    for (int nt = 0; nt < 16; nt++) {
        int c = nt * 8 + v * 2;
        *(float2*)&Og[r * NH + c] =
            make_float2(oacc[nt][0] * inv_lo, oacc[nt][1] * inv_lo);
        *(float2*)&Og[(r + 8) * NH + c] =
            make_float2(oacc[nt][2] * inv_hi, oacc[nt][3] * inv_hi);
    }
}

extern "C" void kernel_launch(void* const* d_in, const int* in_sizes, int n_in,
                              void* d_out, int out_size)
{
    const float* X  = (const float*)d_in[0];
    const float* Wq = (const float*)d_in[1];
    const float* Wk = (const float*)d_in[2];
    const float* Wv = (const float*)d_in[3];
    float* out = (float*)d_out;

    cudaFuncSetAttribute(proj_mma,
        cudaFuncAttributeMaxDynamicSharedMemorySize, PJ_SMEM);
    dim3 pgrid(3, (NB * NS) / 128);
    proj_mma<<<pgrid, 256, PJ_SMEM>>>(X, Wq, Wk, Wv);

    cudaFuncSetAttribute(attn_mma,
        cudaFuncAttributeMaxDynamicSharedMemorySize, AT_SMEM_BYTES);
    dim3 agrid(NS / 128, NB);
    attn_mma<<<agrid, 256, AT_SMEM_BYTES>>>(out);
}

// round 9
// speedup vs baseline: 1.9128x; 1.0637x over previous
#include <cuda_runtime.h>
#include <cuda_fp16.h>
#include <math.h>
#include <stdint.h>

#define NB 16
#define NS 2048
#define ND 1024
#define NH 128

// Split half planes produced by prep/proj
__device__ __half g_qh[(size_t)NB * NS * NH];   // pre-scaled by 128^-0.5
__device__ __half g_ql[(size_t)NB * NS * NH];
__device__ __half g_kh[(size_t)NB * NS * NH];
__device__ __half g_kl[(size_t)NB * NS * NH];
__device__ __half g_vth[(size_t)NB * NH * NS];  // V transposed: [b][h][s]
__device__ __half g_vtl[(size_t)NB * NH * NS];
__device__ __half g_wth[3 * 128 * 1024];        // W^T split: [mat][n][k]
__device__ __half g_wtl[3 * 128 * 1024];

// ---------------------------------------------------------------------------
// Helpers
// ---------------------------------------------------------------------------
__device__ __forceinline__ uint32_t smem_u32(const void* p) {
    uint32_t a;
    asm("{ .reg .u64 t; cvta.to.shared.u64 t, %1; cvt.u32.u64 %0, t; }"
        : "=r"(a) : "l"(p));
    return a;
}

__device__ __forceinline__ void cp16(uint32_t dst, const void* src) {
    uint64_t g;
    asm("cvta.to.global.u64 %0, %1;" : "=l"(g) : "l"(src));
    asm volatile("cp.async.ca.shared.global [%0], [%1], 16;"
                 :: "r"(dst), "l"(g) : "memory");
}

#define CP_COMMIT() asm volatile("cp.async.commit_group;" ::: "memory")
#define CP_WAIT0()  asm volatile("cp.async.wait_group 0;" ::: "memory")

// D += A(16x16) * B(16x8), fp16 inputs, fp32 accumulate
__device__ __forceinline__ void mma_f16(float* c,
    uint32_t a0, uint32_t a1, uint32_t a2, uint32_t a3,
    uint32_t b0, uint32_t b1)
{
    asm volatile(
        "mma.sync.aligned.m16n8k16.row.col.f32.f16.f16.f32 "
        "{%0,%1,%2,%3}, {%4,%5,%6,%7}, {%8,%9}, {%0,%1,%2,%3};"
        : "+f"(c[0]), "+f"(c[1]), "+f"(c[2]), "+f"(c[3])
        : "r"(a0), "r"(a1), "r"(a2), "r"(a3), "r"(b0), "r"(b1));
}

// fp16 3-term split of a float pair -> (hi half2, lo half2)
__device__ __forceinline__ void split_h2(float x, float y,
                                         uint32_t& hi, uint32_t& lo)
{
    __half2 h = __floats2half2_rn(x, y);
    float2 hf = __half22float2(h);
    __half2 l = __floats2half2_rn(x - hf.x, y - hf.y);
    hi = *(uint32_t*)&h;
    lo = *(uint32_t*)&l;
}

// ---------------------------------------------------------------------------
// W prep: W[1024][128] fp32 -> g_wth/g_wtl [mat][n=128][k=1024] half planes
// ---------------------------------------------------------------------------
__global__ void prep_w(const float* __restrict__ Wq,
                       const float* __restrict__ Wk,
                       const float* __restrict__ Wv)
{
    __shared__ float t[32][33];
    const float* W = (blockIdx.z == 0) ? Wq : (blockIdx.z == 1) ? Wk : Wv;
    int k0 = blockIdx.x * 32;
    int n0 = blockIdx.y * 32;
    int lx = threadIdx.x & 31, ly = threadIdx.x >> 5;
#pragma unroll
    for (int i = 0; i < 32; i += 8)
        t[ly + i][lx] = W[(size_t)(k0 + ly + i) * 128 + n0 + lx];
    __syncthreads();
#pragma unroll
    for (int i = 0; i < 32; i += 8) {
        float val = t[lx][ly + i];   // W[k0+lx][n0+ly+i]
        size_t o = ((size_t)blockIdx.z * 128 + n0 + ly + i) * 1024 + k0 + lx;
        __half h = __float2half_rn(val);
        g_wth[o] = h;
        g_wtl[o] = __float2half_rn(val - __half2float(h));
    }
}

// ---------------------------------------------------------------------------
// QKV projection GEMM, fp16x3 on m16n8k16.
// grid (3, 256): bx = matrix (fastest -> X L2 reuse), by = 128-row m-tile.
// CTA 128x128, BK=32, double-buffered cp.async.
// A tile: fp32 [128][stride 36] (split in-register); B: half planes [n][k].
// 8 warps: wm = wid>>1, wn = wid&1; warp tile 32(M) x 64(N).
// ---------------------------------------------------------------------------
#define PJ_AS 36   // fp32 words per A row
#define PJ_BS 56   // halves per B row
#define PJ_A_BYTES (128 * PJ_AS * 4)            // 18432
#define PJ_B_BYTES (128 * PJ_BS * 2)            // 14336 per plane
#define PJ_BUF_BYTES (PJ_A_BYTES + 2 * PJ_B_BYTES)  // 47104
#define PJ_SMEM (2 * PJ_BUF_BYTES)              // 94208

__global__ __launch_bounds__(256, 2)
void proj_mma(const float* __restrict__ X, float* __restrict__ dummy)
{
    extern __shared__ float smf[];
    char* smc = (char*)smf;
    const uint32_t sbase = smem_u32(smf);
    const int tid = threadIdx.x;
    const int wid = tid >> 5;
    const int lane = tid & 31;
    const int u = lane >> 2;
    const int v = lane & 3;
    const int wm = wid >> 1;
    const int wn = wid & 1;

    const int mat = blockIdx.x;
    const size_t m0 = (size_t)blockIdx.y * 128;

    auto copy_tile = [&](int kt, int buf) {
        const int k0 = kt * 32;
        const uint32_t ab  = sbase + buf * PJ_BUF_BYTES;
        const uint32_t bhb = ab + PJ_A_BYTES;
        const uint32_t blb = bhb + PJ_B_BYTES;
#pragma unroll
        for (int i = 0; i < 4; i++) {          // A: 128 rows x 8 x 16B
            int e = i * 256 + tid;
            int row = e >> 3, c = e & 7;
            cp16(ab + (row * PJ_AS + c * 4) * 4,
                 X + (m0 + row) * ND + k0 + c * 4);
        }
#pragma unroll
        for (int i = 0; i < 2; i++) {          // B: 128 rows x 4 x 16B / plane
            int e = i * 256 + tid;
            int row = e >> 2, c = e & 3;
            size_t wo = ((size_t)mat * 128 + row) * 1024 + k0 + c * 8;
            cp16(bhb + (row * PJ_BS + c * 8) * 2, g_wth + wo);
            cp16(blb + (row * PJ_BS + c * 8) * 2, g_wtl + wo);
        }
    };

    float acc[2][8][4];
#pragma unroll
    for (int mt = 0; mt < 2; mt++)
#pragma unroll
        for (int nt = 0; nt < 8; nt++)
#pragma unroll
            for (int j = 0; j < 4; j++) acc[mt][nt][j] = 0.f;

    copy_tile(0, 0);
    CP_COMMIT();

    for (int it = 0; it < 32; it++) {
        const int buf = it & 1;
        CP_WAIT0();
        __syncthreads();
        if (it < 31) {
            copy_tile(it + 1, buf ^ 1);
            CP_COMMIT();
        }

        const float* As = smf + buf * (PJ_BUF_BYTES / 4);
        const __half* Bh = (const __half*)(smc + buf * PJ_BUF_BYTES + PJ_A_BYTES);
        const __half* Bl = Bh + PJ_B_BYTES / 2;

#pragma unroll
        for (int ks = 0; ks < 2; ks++) {
            uint32_t ah[2][4], al[2][4];
#pragma unroll
            for (int mt = 0; mt < 2; mt++) {
                int r = wm * 32 + mt * 16 + u;
                const float* Ap = As + r * PJ_AS + ks * 16 + 2 * v;
                float2 f0 = *(const float2*)Ap;
                float2 f1 = *(const float2*)(Ap + 8 * PJ_AS);
                float2 f2 = *(const float2*)(Ap + 8);
                float2 f3 = *(const float2*)(Ap + 8 * PJ_AS + 8);
                split_h2(f0.x, f0.y, ah[mt][0], al[mt][0]);
                split_h2(f1.x, f1.y, ah[mt][1], al[mt][1]);
                split_h2(f2.x, f2.y, ah[mt][2], al[mt][2]);
                split_h2(f3.x, f3.y, ah[mt][3], al[mt][3]);
            }
#pragma unroll
            for (int nt = 0; nt < 8; nt++) {
                int bn = wn * 64 + nt * 8 + u;
                const __half* bp = Bh + bn * PJ_BS + ks * 16 + 2 * v;
                uint32_t bh0 = *(const uint32_t*)bp;
                uint32_t bh1 = *(const uint32_t*)(bp + 8);
                const __half* bq = Bl + bn * PJ_BS + ks * 16 + 2 * v;
                uint32_t bl0 = *(const uint32_t*)bq;
                uint32_t bl1 = *(const uint32_t*)(bq + 8);
#pragma unroll
                for (int mt = 0; mt < 2; mt++) {
                    mma_f16(acc[mt][nt], ah[mt][0], ah[mt][1], ah[mt][2], ah[mt][3], bh0, bh1);
                    mma_f16(acc[mt][nt], ah[mt][0], ah[mt][1], ah[mt][2], ah[mt][3], bl0, bl1);
                    mma_f16(acc[mt][nt], al[mt][0], al[mt][1], al[mt][2], al[mt][3], bh0, bh1);
                }
            }
        }
    }

    __syncthreads();   // mainloop smem reads complete before any staging

    const float qscale = 0.08838834764831845f;   // 128^-0.5

    if (mat < 2) {
        // Q (scaled) / K: write split half planes [b*s][h]
        __half* Oh = (mat == 0) ? g_qh : g_kh;
        __half* Ol = (mat == 0) ? g_ql : g_kl;
        const float sc = (mat == 0) ? qscale : 1.0f;
#pragma unroll
        for (int mt = 0; mt < 2; mt++) {
#pragma unroll
            for (int nt = 0; nt < 8; nt++) {
                size_t r = m0 + wm * 32 + mt * 16 + u;
                int c = wn * 64 + nt * 8 + 2 * v;
                uint32_t h01, l01, h23, l23;
                split_h2(acc[mt][nt][0] * sc, acc[mt][nt][1] * sc, h01, l01);
                split_h2(acc[mt][nt][2] * sc, acc[mt][nt][3] * sc, h23, l23);
                *(uint32_t*)&Oh[r * NH + c] = h01;
                *(uint32_t*)&Ol[r * NH + c] = l01;
                *(uint32_t*)&Oh[(r + 8) * NH + c] = h23;
                *(uint32_t*)&Ol[(r + 8) * NH + c] = l23;
            }
        }
    } else {
        // V: stage transpose in smem, then write [b][h][s] split planes
        __half* vsh = (__half*)smc;              // [h=128][s=128]
        __half* vsl = vsh + 128 * 128;
#pragma unroll
        for (int mt = 0; mt < 2; mt++) {
#pragma unroll
            for (int nt = 0; nt < 8; nt++) {
#pragma unroll
                for (int j = 0; j < 4; j++) {
                    int r = wm * 32 + mt * 16 + u + (j < 2 ? 0 : 8);
                    int c = wn * 64 + nt * 8 + 2 * v + (j & 1);
                    float val = acc[mt][nt][j];
                    __half h = __float2half_rn(val);
                    vsh[c * 128 + r] = h;
                    vsl[c * 128 + r] = __float2half_rn(val - __half2float(h));
                }
            }
        }
        __syncthreads();
        size_t bb = m0 / NS;
        int s0 = (int)(m0 % NS);
#pragma unroll
        for (int i = 0; i < 8; i++) {
            int e = i * 256 + tid;
            int hrow = e >> 4, ch = e & 15;
            size_t o = (bb * NH + hrow) * NS + s0 + ch * 8;
            *(float4*)&g_vth[o] = *(float4*)&vsh[hrow * 128 + ch * 8];
            *(float4*)&g_vtl[o] = *(float4*)&vsl[hrow * 128 + ch * 8];
        }
    }
}

// ---------------------------------------------------------------------------
// Causal flash attention, fp16x3 on m16n8k16.
// grid (16, 16): qt = 15 - bx (heavy first), b = by. 256 thr, 8 warps.
// BQ=128 (warp owns 16 q-rows), BKV=64, H=128.
// Q fragments in registers; P re-fragmented from S accumulators (no smem).
// K/V double-buffered cp.async, prefetch depth 1.
// smem halves per stage: Kh[64][136] Kl[64][136] Vth[128][72] Vtl[128][72]
// ---------------------------------------------------------------------------
#define AT_KS 136
#define AT_VS 72
#define AT_STAGE_H 35840                         // halves per stage
#define AT_KH(st) ((st) * AT_STAGE_H)
#define AT_KL(st) ((st) * AT_STAGE_H + 8704)
#define AT_VH(st) ((st) * AT_STAGE_H + 17408)
#define AT_VL(st) ((st) * AT_STAGE_H + 26624)
#define AT_QH 35840                              // Q staging in stage 1
#define AT_QL (35840 + 17408)
#define AT_SMEM_BYTES (2 * AT_STAGE_H * 2)       // 143360

__global__ __launch_bounds__(256, 1)
void attn_mma(float* __restrict__ out)
{
    extern __shared__ __half smh[];
    const uint32_t sbase = smem_u32(smh);
    const int tid = threadIdx.x;
    const int wid = tid >> 5;
    const int lane = tid & 31;
    const int u = lane >> 2;
    const int v = lane & 3;

    const int b  = blockIdx.y;
    const int qt = (int)(gridDim.x - 1) - (int)blockIdx.x;
    const int q0 = qt * 128;
    const int njt = 2 * qt + 2;

    const __half* Qhg = g_qh + ((size_t)b * NS + q0) * NH;
    const __half* Qlg = g_ql + ((size_t)b * NS + q0) * NH;

    // ---- stage Q (both planes), extract fragments to registers ----
#pragma unroll
    for (int i = 0; i < 8; i++) {
        int e = i * 256 + tid;
        int row = e >> 4, ch = e & 15;
        cp16(sbase + (AT_QH + row * AT_KS + ch * 8) * 2, Qhg + row * NH + ch * 8);
        cp16(sbase + (AT_QL + row * AT_KS + ch * 8) * 2, Qlg + row * NH + ch * 8);
    }
    CP_COMMIT();
    CP_WAIT0();
    __syncthreads();

    uint32_t qfh[8][4], qfl[8][4];
    {
        const __half* Qs = smh + AT_QH;
        const __half* Ql = smh + AT_QL;
        int r0 = wid * 16 + u;
#pragma unroll
        for (int s = 0; s < 8; s++) {
            int k = s * 16 + 2 * v;
            qfh[s][0] = *(const uint32_t*)&Qs[r0 * AT_KS + k];
            qfh[s][1] = *(const uint32_t*)&Qs[(r0 + 8) * AT_KS + k];
            qfh[s][2] = *(const uint32_t*)&Qs[r0 * AT_KS + k + 8];
            qfh[s][3] = *(const uint32_t*)&Qs[(r0 + 8) * AT_KS + k + 8];
            qfl[s][0] = *(const uint32_t*)&Ql[r0 * AT_KS + k];
            qfl[s][1] = *(const uint32_t*)&Ql[(r0 + 8) * AT_KS + k];
            qfl[s][2] = *(const uint32_t*)&Ql[r0 * AT_KS + k + 8];
            qfl[s][3] = *(const uint32_t*)&Ql[(r0 + 8) * AT_KS + k + 8];
        }
    }
    __syncthreads();   // all warps done reading Q staging

    auto copy_kv = [&](int j, int st) {
        const __half* Khg = g_kh + ((size_t)b * NS + j * 64) * NH;
        const __half* Klg = g_kl + ((size_t)b * NS + j * 64) * NH;
        const __half* Vhg = g_vth + (size_t)b * NH * NS + j * 64;
        const __half* Vlg = g_vtl + (size_t)b * NH * NS + j * 64;
#pragma unroll
        for (int i = 0; i < 4; i++) {      // K: 64 rows x 16 x 16B / plane
            int e = i * 256 + tid;
            int row = e >> 4, ch = e & 15;
            cp16(sbase + (AT_KH(st) + row * AT_KS + ch * 8) * 2, Khg + row * NH + ch * 8);
            cp16(sbase + (AT_KL(st) + row * AT_KS + ch * 8) * 2, Klg + row * NH + ch * 8);
        }
#pragma unroll
        for (int i = 0; i < 4; i++) {      // V^T: 128 rows x 8 x 16B / plane
            int e = i * 256 + tid;
            int row = e >> 3, ch = e & 7;
            cp16(sbase + (AT_VH(st) + row * AT_VS + ch * 8) * 2, Vhg + (size_t)row * NS + ch * 8);
            cp16(sbase + (AT_VL(st) + row * AT_VS + ch * 8) * 2, Vlg + (size_t)row * NS + ch * 8);
        }
    };

    copy_kv(0, 0);
    CP_COMMIT();

    float oacc[16][4];
#pragma unroll
    for (int nt = 0; nt < 16; nt++)
#pragma unroll
        for (int j = 0; j < 4; j++) oacc[nt][j] = 0.f;
    float m_lo = -INFINITY, m_hi = -INFINITY;
    float l_lo = 0.f, l_hi = 0.f;

    for (int jt = 0; jt < njt; jt++) {
        const int st = jt & 1;
        CP_WAIT0();
        __syncthreads();
        if (jt + 1 < njt) {
            copy_kv(jt + 1, st ^ 1);
            CP_COMMIT();
        }

        const __half* Kh = smh + AT_KH(st);
        const __half* Kl = smh + AT_KL(st);
        const __half* Vh = smh + AT_VH(st);
        const __half* Vl = smh + AT_VL(st);

        // ---- S = Q K^T ----
        float sacc[8][4];
#pragma unroll
        for (int nt = 0; nt < 8; nt++)
#pragma unroll
            for (int j = 0; j < 4; j++) sacc[nt][j] = 0.f;

#pragma unroll
        for (int s = 0; s < 8; s++) {
#pragma unroll
            for (int nt = 0; nt < 8; nt++) {
                int bn = nt * 8 + u;
                const __half* kp = Kh + bn * AT_KS + s * 16 + 2 * v;
                uint32_t bh0 = *(const uint32_t*)kp;
                uint32_t bh1 = *(const uint32_t*)(kp + 8);
                const __half* kq = Kl + bn * AT_KS + s * 16 + 2 * v;
                uint32_t bl0 = *(const uint32_t*)kq;
                uint32_t bl1 = *(const uint32_t*)(kq + 8);
                mma_f16(sacc[nt], qfh[s][0], qfh[s][1], qfh[s][2], qfh[s][3], bh0, bh1);
                mma_f16(sacc[nt], qfh[s][0], qfh[s][1], qfh[s][2], qfh[s][3], bl0, bl1);
                mma_f16(sacc[nt], qfl[s][0], qfl[s][1], qfl[s][2], qfl[s][3], bh0, bh1);
            }
        }

        // ---- causal mask (scale already folded into Q) ----
        const int row_lo = q0 + wid * 16 + u;
        const int row_hi = row_lo + 8;
        if (jt >= 2 * qt) {
#pragma unroll
            for (int nt = 0; nt < 8; nt++) {
#pragma unroll
                for (int j = 0; j < 4; j++) {
                    int col = jt * 64 + nt * 8 + 2 * v + (j & 1);
                    int row = (j < 2) ? row_lo : row_hi;
                    if (col > row) sacc[nt][j] = -INFINITY;
                }
            }
        }

        // ---- online softmax ----
        float mx_lo = -INFINITY, mx_hi = -INFINITY;
#pragma unroll
        for (int nt = 0; nt < 8; nt++) {
            mx_lo = fmaxf(mx_lo, fmaxf(sacc[nt][0], sacc[nt][1]));
            mx_hi = fmaxf(mx_hi, fmaxf(sacc[nt][2], sacc[nt][3]));
        }
        mx_lo = fmaxf(mx_lo, __shfl_xor_sync(0xffffffffu, mx_lo, 1));
        mx_lo = fmaxf(mx_lo, __shfl_xor_sync(0xffffffffu, mx_lo, 2));
        mx_hi = fmaxf(mx_hi, __shfl_xor_sync(0xffffffffu, mx_hi, 1));
        mx_hi = fmaxf(mx_hi, __shfl_xor_sync(0xffffffffu, mx_hi, 2));

        float mn_lo = fmaxf(m_lo, mx_lo);
        float mn_hi = fmaxf(m_hi, mx_hi);
        float sc_lo = __expf(m_lo - mn_lo);
        float sc_hi = __expf(m_hi - mn_hi);
        m_lo = mn_lo; m_hi = mn_hi;

        float rs_lo = 0.f, rs_hi = 0.f;
#pragma unroll
        for (int nt = 0; nt < 8; nt++) {
            sacc[nt][0] = __expf(sacc[nt][0] - mn_lo);
            sacc[nt][1] = __expf(sacc[nt][1] - mn_lo);
            sacc[nt][2] = __expf(sacc[nt][2] - mn_hi);
            sacc[nt][3] = __expf(sacc[nt][3] - mn_hi);
            rs_lo += sacc[nt][0] + sacc[nt][1];
            rs_hi += sacc[nt][2] + sacc[nt][3];
        }
        rs_lo += __shfl_xor_sync(0xffffffffu, rs_lo, 1);
        rs_lo += __shfl_xor_sync(0xffffffffu, rs_lo, 2);
        rs_hi += __shfl_xor_sync(0xffffffffu, rs_hi, 1);
        rs_hi += __shfl_xor_sync(0xffffffffu, rs_hi, 2);
        l_lo = l_lo * sc_lo + rs_lo;
        l_hi = l_hi * sc_hi + rs_hi;

#pragma unroll
        for (int nt = 0; nt < 16; nt++) {
            oacc[nt][0] *= sc_lo; oacc[nt][1] *= sc_lo;
            oacc[nt][2] *= sc_hi; oacc[nt][3] *= sc_hi;
        }

        // ---- O += P V : P A-fragments straight from sacc registers ----
#pragma unroll
        for (int s2 = 0; s2 < 4; s2++) {
            uint32_t ph[4], pl[4];
            split_h2(sacc[2 * s2][0],     sacc[2 * s2][1],     ph[0], pl[0]);
            split_h2(sacc[2 * s2][2],     sacc[2 * s2][3],     ph[1], pl[1]);
            split_h2(sacc[2 * s2 + 1][0], sacc[2 * s2 + 1][1], ph[2], pl[2]);
            split_h2(sacc[2 * s2 + 1][2], sacc[2 * s2 + 1][3], ph[3], pl[3]);
#pragma unroll
            for (int nt = 0; nt < 16; nt++) {
                int vn = nt * 8 + u;
                const __half* vp = Vh + vn * AT_VS + s2 * 16 + 2 * v;
                uint32_t vh0 = *(const uint32_t*)vp;
                uint32_t vh1 = *(const uint32_t*)(vp + 8);
                const __half* vq = Vl + vn * AT_VS + s2 * 16 + 2 * v;
                uint32_t vl0 = *(const uint32_t*)vq;
                uint32_t vl1 = *(const uint32_t*)(vq + 8);
                mma_f16(oacc[nt], ph[0], ph[1], ph[2], ph[3], vh0, vh1);
                mma_f16(oacc[nt], ph[0], ph[1], ph[2], ph[3], vl0, vl1);
                mma_f16(oacc[nt], pl[0], pl[1], pl[2], pl[3], vh0, vh1);
            }
        }
    }

    // ---- normalize + write ----
    float inv_lo = 1.0f / l_lo;
    float inv_hi = 1.0f / l_hi;
    float* Og = out + ((size_t)b * NS + q0) * NH;
    int r = wid * 16 + u;
#pragma unroll
    for (int nt = 0; nt < 16; nt++) {
        int c = nt * 8 + 2 * v;
        *(float2*)&Og[r * NH + c] =
            make_float2(oacc[nt][0] * inv_lo, oacc[nt][1] * inv_lo);
        *(float2*)&Og[(r + 8) * NH + c] =
            make_float2(oacc[nt][2] * inv_hi, oacc[nt][3] * inv_hi);
    }
}

extern "C" void kernel_launch(void* const* d_in, const int* in_sizes, int n_in,
                              void* d_out, int out_size)
{
    const float* X  = (const float*)d_in[0];
    const float* Wq = (const float*)d_in[1];
    const float* Wk = (const float*)d_in[2];
    const float* Wv = (const float*)d_in[3];
    float* out = (float*)d_out;

    // 1) split + transpose weights
    dim3 wgrid(32, 4, 3);
    prep_w<<<wgrid, 256>>>(Wq, Wk, Wv);

    // 2) QKV projection (fp16x3), writes split/scaled/transposed planes
    cudaFuncSetAttribute(proj_mma,
        cudaFuncAttributeMaxDynamicSharedMemorySize, PJ_SMEM);
    dim3 pgrid(3, (NB * NS) / 128);
    proj_mma<<<pgrid, 256, PJ_SMEM>>>(X, nullptr);

    // 3) attention (fp16x3)
    cudaFuncSetAttribute(attn_mma,
        cudaFuncAttributeMaxDynamicSharedMemorySize, AT_SMEM_BYTES);
    dim3 agrid(NS / 128, NB);
    attn_mma<<<agrid, 256, AT_SMEM_BYTES>>>(out);
}

// round 12
// speedup vs baseline: 2.8595x; 1.4949x over previous
#include <cuda_runtime.h>
#include <cuda_fp16.h>
#include <math.h>
#include <stdint.h>

#define NB 16
#define NS 2048
#define ND 1024
#define NH 128

// Split half planes produced by prep/proj
__device__ __half g_qh[(size_t)NB * NS * NH];   // pre-scaled by 128^-0.5
__device__ __half g_ql[(size_t)NB * NS * NH];
__device__ __half g_kh[(size_t)NB * NS * NH];
__device__ __half g_kl[(size_t)NB * NS * NH];
__device__ __half g_vth[(size_t)NB * NH * NS];  // V transposed: [b][h][s]
__device__ __half g_vtl[(size_t)NB * NH * NS];
__device__ __half g_wth[3 * 128 * 1024];        // W^T split: [mat][n][k]
__device__ __half g_wtl[3 * 128 * 1024];

// ---------------------------------------------------------------------------
// Helpers
// ---------------------------------------------------------------------------
__device__ __forceinline__ uint32_t smem_u32(const void* p) {
    uint32_t a;
    asm("{ .reg .u64 t; cvta.to.shared.u64 t, %1; cvt.u32.u64 %0, t; }"
        : "=r"(a) : "l"(p));
    return a;
}

__device__ __forceinline__ void cp16(uint32_t dst, const void* src) {
    uint64_t g;
    asm("cvta.to.global.u64 %0, %1;" : "=l"(g) : "l"(src));
    asm volatile("cp.async.ca.shared.global [%0], [%1], 16;"
                 :: "r"(dst), "l"(g) : "memory");
}

#define CP_COMMIT() asm volatile("cp.async.commit_group;" ::: "memory")
#define CP_WAIT0()  asm volatile("cp.async.wait_group 0;" ::: "memory")
#define CP_WAIT1()  asm volatile("cp.async.wait_group 1;" ::: "memory")
#define CP_WAIT2()  asm volatile("cp.async.wait_group 2;" ::: "memory")

// D += A(16x16) * B(16x8), fp16 inputs, fp32 accumulate
__device__ __forceinline__ void mma_f16(float* c,
    uint32_t a0, uint32_t a1, uint32_t a2, uint32_t a3,
    uint32_t b0, uint32_t b1)
{
    asm volatile(
        "mma.sync.aligned.m16n8k16.row.col.f32.f16.f16.f32 "
        "{%0,%1,%2,%3}, {%4,%5,%6,%7}, {%8,%9}, {%0,%1,%2,%3};"
        : "+f"(c[0]), "+f"(c[1]), "+f"(c[2]), "+f"(c[3])
        : "r"(a0), "r"(a1), "r"(a2), "r"(a3), "r"(b0), "r"(b1));
}

// fp16 3-term split of a float pair -> (hi half2, lo half2)
__device__ __forceinline__ void split_h2(float x, float y,
                                         uint32_t& hi, uint32_t& lo)
{
    __half2 h = __floats2half2_rn(x, y);
    float2 hf = __half22float2(h);
    __half2 l = __floats2half2_rn(x - hf.x, y - hf.y);
    hi = *(uint32_t*)&h;
    lo = *(uint32_t*)&l;
}

// ---------------------------------------------------------------------------
// W prep: W[1024][128] fp32 -> g_wth/g_wtl [mat][n=128][k=1024] half planes
// ---------------------------------------------------------------------------
__global__ void prep_w(const float* __restrict__ Wq,
                       const float* __restrict__ Wk,
                       const float* __restrict__ Wv)
{
    __shared__ float t[32][33];
    const float* W = (blockIdx.z == 0) ? Wq : (blockIdx.z == 1) ? Wk : Wv;
    int k0 = blockIdx.x * 32;
    int n0 = blockIdx.y * 32;
    int lx = threadIdx.x & 31, ly = threadIdx.x >> 5;
#pragma unroll
    for (int i = 0; i < 32; i += 8)
        t[ly + i][lx] = W[(size_t)(k0 + ly + i) * 128 + n0 + lx];
    __syncthreads();
#pragma unroll
    for (int i = 0; i < 32; i += 8) {
        float val = t[lx][ly + i];   // W[k0+lx][n0+ly+i]
        size_t o = ((size_t)blockIdx.z * 128 + n0 + ly + i) * 1024 + k0 + lx;
        __half h = __float2half_rn(val);
        g_wth[o] = h;
        g_wtl[o] = __float2half_rn(val - __half2float(h));
    }
}

// ---------------------------------------------------------------------------
// QKV projection GEMM, fp16x3 on m16n8k16 (unchanged from round 9).
// ---------------------------------------------------------------------------
#define PJ_AS 36
#define PJ_BS 56
#define PJ_A_BYTES (128 * PJ_AS * 4)
#define PJ_B_BYTES (128 * PJ_BS * 2)
#define PJ_BUF_BYTES (PJ_A_BYTES + 2 * PJ_B_BYTES)
#define PJ_SMEM (2 * PJ_BUF_BYTES)

__global__ __launch_bounds__(256, 2)
void proj_mma(const float* __restrict__ X, float* __restrict__ dummy)
{
    extern __shared__ float smf[];
    char* smc = (char*)smf;
    const uint32_t sbase = smem_u32(smf);
    const int tid = threadIdx.x;
    const int wid = tid >> 5;
    const int lane = tid & 31;
    const int u = lane >> 2;
    const int v = lane & 3;
    const int wm = wid >> 1;
    const int wn = wid & 1;

    const int mat = blockIdx.x;
    const size_t m0 = (size_t)blockIdx.y * 128;

    auto copy_tile = [&](int kt, int buf) {
        const int k0 = kt * 32;
        const uint32_t ab  = sbase + buf * PJ_BUF_BYTES;
        const uint32_t bhb = ab + PJ_A_BYTES;
        const uint32_t blb = bhb + PJ_B_BYTES;
#pragma unroll
        for (int i = 0; i < 4; i++) {
            int e = i * 256 + tid;
            int row = e >> 3, c = e & 7;
            cp16(ab + (row * PJ_AS + c * 4) * 4,
                 X + (m0 + row) * ND + k0 + c * 4);
        }
#pragma unroll
        for (int i = 0; i < 2; i++) {
            int e = i * 256 + tid;
            int row = e >> 2, c = e & 3;
            size_t wo = ((size_t)mat * 128 + row) * 1024 + k0 + c * 8;
            cp16(bhb + (row * PJ_BS + c * 8) * 2, g_wth + wo);
            cp16(blb + (row * PJ_BS + c * 8) * 2, g_wtl + wo);
        }
    };

    float acc[2][8][4];
#pragma unroll
    for (int mt = 0; mt < 2; mt++)
#pragma unroll
        for (int nt = 0; nt < 8; nt++)
#pragma unroll
            for (int j = 0; j < 4; j++) acc[mt][nt][j] = 0.f;

    copy_tile(0, 0);
    CP_COMMIT();

    for (int it = 0; it < 32; it++) {
        const int buf = it & 1;
        CP_WAIT0();
        __syncthreads();
        if (it < 31) {
            copy_tile(it + 1, buf ^ 1);
            CP_COMMIT();
        }

        const float* As = smf + buf * (PJ_BUF_BYTES / 4);
        const __half* Bh = (const __half*)(smc + buf * PJ_BUF_BYTES + PJ_A_BYTES);
        const __half* Bl = Bh + PJ_B_BYTES / 2;

#pragma unroll
        for (int ks = 0; ks < 2; ks++) {
            uint32_t ah[2][4], al[2][4];
#pragma unroll
            for (int mt = 0; mt < 2; mt++) {
                int r = wm * 32 + mt * 16 + u;
                const float* Ap = As + r * PJ_AS + ks * 16 + 2 * v;
                float2 f0 = *(const float2*)Ap;
                float2 f1 = *(const float2*)(Ap + 8 * PJ_AS);
                float2 f2 = *(const float2*)(Ap + 8);
                float2 f3 = *(const float2*)(Ap + 8 * PJ_AS + 8);
                split_h2(f0.x, f0.y, ah[mt][0], al[mt][0]);
                split_h2(f1.x, f1.y, ah[mt][1], al[mt][1]);
                split_h2(f2.x, f2.y, ah[mt][2], al[mt][2]);
                split_h2(f3.x, f3.y, ah[mt][3], al[mt][3]);
            }
#pragma unroll
            for (int nt = 0; nt < 8; nt++) {
                int bn = wn * 64 + nt * 8 + u;
                const __half* bp = Bh + bn * PJ_BS + ks * 16 + 2 * v;
                uint32_t bh0 = *(const uint32_t*)bp;
                uint32_t bh1 = *(const uint32_t*)(bp + 8);
                const __half* bq = Bl + bn * PJ_BS + ks * 16 + 2 * v;
                uint32_t bl0 = *(const uint32_t*)bq;
                uint32_t bl1 = *(const uint32_t*)(bq + 8);
#pragma unroll
                for (int mt = 0; mt < 2; mt++) {
                    mma_f16(acc[mt][nt], ah[mt][0], ah[mt][1], ah[mt][2], ah[mt][3], bh0, bh1);
                    mma_f16(acc[mt][nt], ah[mt][0], ah[mt][1], ah[mt][2], ah[mt][3], bl0, bl1);
                    mma_f16(acc[mt][nt], al[mt][0], al[mt][1], al[mt][2], al[mt][3], bh0, bh1);
                }
            }
        }
    }

    __syncthreads();

    const float qscale = 0.08838834764831845f;

    if (mat < 2) {
        __half* Oh = (mat == 0) ? g_qh : g_kh;
        __half* Ol = (mat == 0) ? g_ql : g_kl;
        const float sc = (mat == 0) ? qscale : 1.0f;
#pragma unroll
        for (int mt = 0; mt < 2; mt++) {
#pragma unroll
            for (int nt = 0; nt < 8; nt++) {
                size_t r = m0 + wm * 32 + mt * 16 + u;
                int c = wn * 64 + nt * 8 + 2 * v;
                uint32_t h01, l01, h23, l23;
                split_h2(acc[mt][nt][0] * sc, acc[mt][nt][1] * sc, h01, l01);
                split_h2(acc[mt][nt][2] * sc, acc[mt][nt][3] * sc, h23, l23);
                *(uint32_t*)&Oh[r * NH + c] = h01;
                *(uint32_t*)&Ol[r * NH + c] = l01;
                *(uint32_t*)&Oh[(r + 8) * NH + c] = h23;
                *(uint32_t*)&Ol[(r + 8) * NH + c] = l23;
            }
        }
    } else {
        __half* vsh = (__half*)smc;
        __half* vsl = vsh + 128 * 128;
#pragma unroll
        for (int mt = 0; mt < 2; mt++) {
#pragma unroll
            for (int nt = 0; nt < 8; nt++) {
#pragma unroll
                for (int j = 0; j < 4; j++) {
                    int r = wm * 32 + mt * 16 + u + (j < 2 ? 0 : 8);
                    int c = wn * 64 + nt * 8 + 2 * v + (j & 1);
                    float val = acc[mt][nt][j];
                    __half h = __float2half_rn(val);
                    vsh[c * 128 + r] = h;
                    vsl[c * 128 + r] = __float2half_rn(val - __half2float(h));
                }
            }
        }
        __syncthreads();
        size_t bb = m0 / NS;
        int s0 = (int)(m0 % NS);
#pragma unroll
        for (int i = 0; i < 8; i++) {
            int e = i * 256 + tid;
            int hrow = e >> 4, ch = e & 15;
            size_t o = (bb * NH + hrow) * NS + s0 + ch * 8;
            *(float4*)&g_vth[o] = *(float4*)&vsh[hrow * 128 + ch * 8];
            *(float4*)&g_vtl[o] = *(float4*)&vsl[hrow * 128 + ch * 8];
        }
    }
}

// ---------------------------------------------------------------------------
// Causal flash attention, fp16x3, 2 CTAs/SM.
// CTA: 128 threads (4 warps), BQ=64 (warp owns 16 q-rows), BKV=64, H=128.
// grid (32, 16): qt = 31 - bx (heavy first), b = by.
// K double-buffered (prefetch depth 1); V single-buffered (its cp.async
// overlaps the S phase). Q fragments in registers; P from S registers.
// smem (halves): K[2]{h[64][136], l} | V{h[128][72], l}  -> 104 KB
// Q staged transiently in the V area before the mainloop.
// ---------------------------------------------------------------------------
#define AT_KS 136
#define AT_VS 72
#define AT_KH(st) ((st) * 17408)
#define AT_KL(st) ((st) * 17408 + 8704)
#define AT_V  34816
#define AT_VH (AT_V)
#define AT_VL (AT_V + 9216)
#define AT_QH (AT_V)
#define AT_QL (AT_V + 8704)
#define AT_SMEM_BYTES ((34816 + 18432) * 2)      // 106496

__global__ __launch_bounds__(128, 2)
void attn_mma(float* __restrict__ out)
{
    extern __shared__ __half smh[];
    const uint32_t sbase = smem_u32(smh);
    const int tid = threadIdx.x;
    const int wid = tid >> 5;
    const int lane = tid & 31;
    const int u = lane >> 2;
    const int v = lane & 3;

    const int b  = blockIdx.y;
    const int qt = (int)(gridDim.x - 1) - (int)blockIdx.x;  // heavy first
    const int q0 = qt * 64;
    const int njt = qt + 1;

    const __half* Qhg = g_qh + ((size_t)b * NS + q0) * NH;
    const __half* Qlg = g_ql + ((size_t)b * NS + q0) * NH;
    const __half* Khg = g_kh + (size_t)b * NS * NH;
    const __half* Klg = g_kl + (size_t)b * NS * NH;
    const __half* Vhg = g_vth + (size_t)b * NH * NS;
    const __half* Vlg = g_vtl + (size_t)b * NH * NS;

    // ---- stage Q (both planes) into the V area, extract register frags ----
#pragma unroll
    for (int i = 0; i < 8; i++) {
        int e = i * 128 + tid;
        int row = e >> 4, ch = e & 15;          // 64 rows x 16 chunks
        cp16(sbase + (AT_QH + row * AT_KS + ch * 8) * 2, Qhg + row * NH + ch * 8);
        cp16(sbase + (AT_QL + row * AT_KS + ch * 8) * 2, Qlg + row * NH + ch * 8);
    }
    CP_COMMIT();
    CP_WAIT0();
    __syncthreads();

    uint32_t qfh[8][4], qfl[8][4];
    {
        const __half* Qs = smh + AT_QH;
        const __half* Ql = smh + AT_QL;
        int r0 = wid * 16 + u;
#pragma unroll
        for (int s = 0; s < 8; s++) {
            int k = s * 16 + 2 * v;
            qfh[s][0] = *(const uint32_t*)&Qs[r0 * AT_KS + k];
            qfh[s][1] = *(const uint32_t*)&Qs[(r0 + 8) * AT_KS + k];
            qfh[s][2] = *(const uint32_t*)&Qs[r0 * AT_KS + k + 8];
            qfh[s][3] = *(const uint32_t*)&Qs[(r0 + 8) * AT_KS + k + 8];
            qfl[s][0] = *(const uint32_t*)&Ql[r0 * AT_KS + k];
            qfl[s][1] = *(const uint32_t*)&Ql[(r0 + 8) * AT_KS + k];
            qfl[s][2] = *(const uint32_t*)&Ql[r0 * AT_KS + k + 8];
            qfl[s][3] = *(const uint32_t*)&Ql[(r0 + 8) * AT_KS + k + 8];
        }
    }

    auto copy_k = [&](int j, int st) {
        const __half* kh = Khg + (size_t)(j * 64) * NH;
        const __half* kl = Klg + (size_t)(j * 64) * NH;
#pragma unroll
        for (int i = 0; i < 8; i++) {           // 64 rows x 16 chunks / plane
            int e = i * 128 + tid;
            int row = e >> 4, ch = e & 15;
            cp16(sbase + (AT_KH(st) + row * AT_KS + ch * 8) * 2, kh + row * NH + ch * 8);
            cp16(sbase + (AT_KL(st) + row * AT_KS + ch * 8) * 2, kl + row * NH + ch * 8);
        }
    };
    auto copy_v = [&](int j) {
        const __half* vh = Vhg + j * 64;
        const __half* vl = Vlg + j * 64;
#pragma unroll
        for (int i = 0; i < 8; i++) {           // 128 rows x 8 chunks / plane
            int e = i * 128 + tid;
            int row = e >> 3, ch = e & 7;
            cp16(sbase + (AT_VH + row * AT_VS + ch * 8) * 2, vh + (size_t)row * NS + ch * 8);
            cp16(sbase + (AT_VL + row * AT_VS + ch * 8) * 2, vl + (size_t)row * NS + ch * 8);
        }
    };

    float oacc[16][4];
#pragma unroll
    for (int nt = 0; nt < 16; nt++)
#pragma unroll
        for (int j = 0; j < 4; j++) oacc[nt][j] = 0.f;
    float m_lo = -INFINITY, m_hi = -INFINITY;
    float l_lo = 0.f, l_hi = 0.f;

    // groups in flight are tracked by commit order:
    //   ... K(jt) | V(jt), K(jt+1) | V(jt+1), K(jt+2) | ...
    copy_k(0, 0);
    CP_COMMIT();

    for (int jt = 0; jt < njt; jt++) {
        const int st = jt & 1;
        const bool pk = (jt + 1 < njt);

        __syncthreads();          // PV(jt-1)/S(jt-1) done -> V and K(st^1) free
        copy_v(jt);
        CP_COMMIT();
        if (pk) {
            copy_k(jt + 1, st ^ 1);
            CP_COMMIT();
        }
        // ensure K(jt) arrived: leave at most {V(jt), K(jt+1)} pending
        if (pk) CP_WAIT2(); else CP_WAIT1();
        __syncthreads();

        const __half* Kh = smh + AT_KH(st);
        const __half* Kl = smh + AT_KL(st);

        // ---- S = Q K^T ----
        float sacc[8][4];
#pragma unroll
        for (int nt = 0; nt < 8; nt++)
#pragma unroll
            for (int j = 0; j < 4; j++) sacc[nt][j] = 0.f;

#pragma unroll
        for (int s = 0; s < 8; s++) {
#pragma unroll
            for (int nt = 0; nt < 8; nt++) {
                int bn = nt * 8 + u;
                const __half* kp = Kh + bn * AT_KS + s * 16 + 2 * v;
                uint32_t bh0 = *(const uint32_t*)kp;
                uint32_t bh1 = *(const uint32_t*)(kp + 8);
                const __half* kq = Kl + bn * AT_KS + s * 16 + 2 * v;
                uint32_t bl0 = *(const uint32_t*)kq;
                uint32_t bl1 = *(const uint32_t*)(kq + 8);
                mma_f16(sacc[nt], qfh[s][0], qfh[s][1], qfh[s][2], qfh[s][3], bh0, bh1);
                mma_f16(sacc[nt], qfh[s][0], qfh[s][1], qfh[s][2], qfh[s][3], bl0, bl1);
                mma_f16(sacc[nt], qfl[s][0], qfl[s][1], qfl[s][2], qfl[s][3], bh0, bh1);
            }
        }

        // ---- causal mask (diagonal tile only; scale folded into Q) ----
        if (jt == njt - 1) {
            const int row_lo = q0 + wid * 16 + u;
            const int row_hi = row_lo + 8;
#pragma unroll
            for (int nt = 0; nt < 8; nt++) {
#pragma unroll
                for (int j = 0; j < 4; j++) {
                    int col = jt * 64 + nt * 8 + 2 * v + (j & 1);
                    int row = (j < 2) ? row_lo : row_hi;
                    if (col > row) sacc[nt][j] = -INFINITY;
                }
            }
        }

        // ---- online softmax ----
        float mx_lo = -INFINITY, mx_hi = -INFINITY;
#pragma unroll
        for (int nt = 0; nt < 8; nt++) {
            mx_lo = fmaxf(mx_lo, fmaxf(sacc[nt][0], sacc[nt][1]));
            mx_hi = fmaxf(mx_hi, fmaxf(sacc[nt][2], sacc[nt][3]));
        }
        mx_lo = fmaxf(mx_lo, __shfl_xor_sync(0xffffffffu, mx_lo, 1));
        mx_lo = fmaxf(mx_lo, __shfl_xor_sync(0xffffffffu, mx_lo, 2));
        mx_hi = fmaxf(mx_hi, __shfl_xor_sync(0xffffffffu, mx_hi, 1));
        mx_hi = fmaxf(mx_hi, __shfl_xor_sync(0xffffffffu, mx_hi, 2));

        float mn_lo = fmaxf(m_lo, mx_lo);
        float mn_hi = fmaxf(m_hi, mx_hi);
        float sc_lo = __expf(m_lo - mn_lo);
        float sc_hi = __expf(m_hi - mn_hi);
        m_lo = mn_lo; m_hi = mn_hi;

        float rs_lo = 0.f, rs_hi = 0.f;
#pragma unroll
        for (int nt = 0; nt < 8; nt++) {
            sacc[nt][0] = __expf(sacc[nt][0] - mn_lo);
            sacc[nt][1] = __expf(sacc[nt][1] - mn_lo);
            sacc[nt][2] = __expf(sacc[nt][2] - mn_hi);
            sacc[nt][3] = __expf(sacc[nt][3] - mn_hi);
            rs_lo += sacc[nt][0] + sacc[nt][1];
            rs_hi += sacc[nt][2] + sacc[nt][3];
        }
        rs_lo += __shfl_xor_sync(0xffffffffu, rs_lo, 1);
        rs_lo += __shfl_xor_sync(0xffffffffu, rs_lo, 2);
        rs_hi += __shfl_xor_sync(0xffffffffu, rs_hi, 1);
        rs_hi += __shfl_xor_sync(0xffffffffu, rs_hi, 2);
        l_lo = l_lo * sc_lo + rs_lo;
        l_hi = l_hi * sc_hi + rs_hi;

#pragma unroll
        for (int nt = 0; nt < 16; nt++) {
            oacc[nt][0] *= sc_lo; oacc[nt][1] *= sc_lo;
            oacc[nt][2] *= sc_hi; oacc[nt][3] *= sc_hi;
        }

        // ensure V(jt) arrived: leave at most {K(jt+1)} pending
        if (pk) CP_WAIT1(); else CP_WAIT0();
        __syncthreads();

        const __half* Vh = smh + AT_VH;
        const __half* Vl = smh + AT_VL;

        // ---- O += P V : P A-fragments straight from sacc registers ----
#pragma unroll
        for (int s2 = 0; s2 < 4; s2++) {
            uint32_t ph[4], pl[4];
            split_h2(sacc[2 * s2][0],     sacc[2 * s2][1],     ph[0], pl[0]);
            split_h2(sacc[2 * s2][2],     sacc[2 * s2][3],     ph[1], pl[1]);
            split_h2(sacc[2 * s2 + 1][0], sacc[2 * s2 + 1][1], ph[2], pl[2]);
            split_h2(sacc[2 * s2 + 1][2], sacc[2 * s2 + 1][3], ph[3], pl[3]);
#pragma unroll
            for (int nt = 0; nt < 16; nt++) {
                int vn = nt * 8 + u;
                const __half* vp = Vh + vn * AT_VS + s2 * 16 + 2 * v;
                uint32_t vh0 = *(const uint32_t*)vp;
                uint32_t vh1 = *(const uint32_t*)(vp + 8);
                const __half* vq = Vl + vn * AT_VS + s2 * 16 + 2 * v;
                uint32_t vl0 = *(const uint32_t*)vq;
                uint32_t vl1 = *(const uint32_t*)(vq + 8);
                mma_f16(oacc[nt], ph[0], ph[1], ph[2], ph[3], vh0, vh1);
                mma_f16(oacc[nt], ph[0], ph[1], ph[2], ph[3], vl0, vl1);
                mma_f16(oacc[nt], pl[0], pl[1], pl[2], pl[3], vh0, vh1);
            }
        }
    }

    // ---- normalize + write ----
    float inv_lo = 1.0f / l_lo;
    float inv_hi = 1.0f / l_hi;
    float* Og = out + ((size_t)b * NS + q0) * NH;
    int r = wid * 16 + u;
#pragma unroll
    for (int nt = 0; nt < 16; nt++) {
        int c = nt * 8 + 2 * v;
        *(float2*)&Og[r * NH + c] =
            make_float2(oacc[nt][0] * inv_lo, oacc[nt][1] * inv_lo);
        *(float2*)&Og[(r + 8) * NH + c] =
            make_float2(oacc[nt][2] * inv_hi, oacc[nt][3] * inv_hi);
    }
}

extern "C" void kernel_launch(void* const* d_in, const int* in_sizes, int n_in,
                              void* d_out, int out_size)
{
    const float* X  = (const float*)d_in[0];
    const float* Wq = (const float*)d_in[1];
    const float* Wk = (const float*)d_in[2];
    const float* Wv = (const float*)d_in[3];
    float* out = (float*)d_out;

    // 1) split + transpose weights
    dim3 wgrid(32, 4, 3);
    prep_w<<<wgrid, 256>>>(Wq, Wk, Wv);

    // 2) QKV projection (fp16x3)
    cudaFuncSetAttribute(proj_mma,
        cudaFuncAttributeMaxDynamicSharedMemorySize, PJ_SMEM);
    dim3 pgrid(3, (NB * NS) / 128);
    proj_mma<<<pgrid, 256, PJ_SMEM>>>(X, nullptr);

    // 3) attention (fp16x3), 2 CTAs/SM
    cudaFuncSetAttribute(attn_mma,
        cudaFuncAttributeMaxDynamicSharedMemorySize, AT_SMEM_BYTES);
    dim3 agrid(NS / 64, NB);
    attn_mma<<<agrid, 128, AT_SMEM_BYTES>>>(out);
}